// round 1
// baseline (speedup 1.0000x reference)
#include <cuda_runtime.h>
#include <cuda_bf16.h>

#define D_MODEL 1024
#define NHEAD   16
#define DK      64
#define BATCH   2
#define SEQ     2048
#define M_TOT   (BATCH*SEQ)   // 4096

// Scratch (allocation-free rule: __device__ globals)
__device__ float g_q[(size_t)BATCH*SEQ*D_MODEL];
__device__ float g_k[(size_t)BATCH*SEQ*D_MODEL];
__device__ float g_v[(size_t)BATCH*SEQ*D_MODEL];
__device__ float g_o[(size_t)BATCH*SEQ*D_MODEL];

// ---------------------------------------------------------------------------
// SGEMM: C[M,N] = A[M,K] * B[N,K]^T   (B row-major [N,K], i.e. y = x @ W^T)
// 64x64 tile, BK=16, 256 threads, 4x4 micro-tile per thread.
// gridDim.z selects among up to 3 (B,C) pairs so QKV shares one launch.
// ---------------------------------------------------------------------------
#define BM 64
#define BN 64
#define BK 16

__global__ __launch_bounds__(256) void sgemm_abT(
    const float* __restrict__ A,
    const float* __restrict__ B0, const float* __restrict__ B1, const float* __restrict__ B2,
    float* __restrict__ C0, float* __restrict__ C1, float* __restrict__ C2,
    int M, int N, int K)
{
    const float* B; float* C;
    if (blockIdx.z == 0)      { B = B0; C = C0; }
    else if (blockIdx.z == 1) { B = B1; C = C1; }
    else                      { B = B2; C = C2; }

    __shared__ float As[BK][BM + 1];
    __shared__ float Bs[BK][BN + 1];

    const int tid = threadIdx.x;
    const int tx = tid & 15;      // 0..15 -> N
    const int ty = tid >> 4;      // 0..15 -> M
    const int row0 = blockIdx.y * BM;
    const int col0 = blockIdx.x * BN;

    float acc[4][4] = {};

    for (int k0 = 0; k0 < K; k0 += BK) {
        #pragma unroll
        for (int i = 0; i < 4; i++) {
            int idx = tid + i * 256;          // 0..1023
            int r  = idx >> 4;                // 0..63
            int kk = idx & 15;                // 0..15
            As[kk][r] = A[(size_t)(row0 + r) * K + k0 + kk];
            Bs[kk][r] = B[(size_t)(col0 + r) * K + k0 + kk];
        }
        __syncthreads();

        #pragma unroll
        for (int kk = 0; kk < BK; kk++) {
            float a[4], b[4];
            #pragma unroll
            for (int i = 0; i < 4; i++) a[i] = As[kk][ty * 4 + i];
            #pragma unroll
            for (int j = 0; j < 4; j++) b[j] = Bs[kk][tx * 4 + j];
            #pragma unroll
            for (int i = 0; i < 4; i++)
                #pragma unroll
                for (int j = 0; j < 4; j++)
                    acc[i][j] += a[i] * b[j];
        }
        __syncthreads();
    }

    #pragma unroll
    for (int i = 0; i < 4; i++) {
        #pragma unroll
        for (int j = 0; j < 4; j++) {
            C[(size_t)(row0 + ty * 4 + i) * N + col0 + tx * 4 + j] = acc[i][j];
        }
    }
}

// ---------------------------------------------------------------------------
// RoPE in-place on Q and K. Layout: [b*SEQ+s][h*64 + d], interleaved pairs.
// angle = pos * theta^(-2i/64);  (e,o) -> (e*cos - o*sin, e*sin + o*cos)
// ---------------------------------------------------------------------------
__global__ void rope_kernel(float* __restrict__ q, float* __restrict__ k,
                            const int* __restrict__ pos)
{
    int idx = blockIdx.x * blockDim.x + threadIdx.x;   // over B*S*H*(DK/2)
    if (idx >= BATCH * SEQ * NHEAD * (DK / 2)) return;
    int i  = idx & 31;            // pair index within head
    int h  = (idx >> 5) & 15;
    int bs = idx >> 9;            // b*SEQ + s
    int p  = pos[bs];

    // inv_freq = 10000^(-2i/64) = exp(-(2i/64)*ln(10000))
    float inv = __expf(-(float)(2 * i) * (9.210340371976184f / 64.0f));
    float ang = (float)p * inv;
    float sn, cs;
    sincosf(ang, &sn, &cs);

    size_t off = (size_t)bs * D_MODEL + h * DK + 2 * i;
    float e = q[off], o = q[off + 1];
    q[off]     = e * cs - o * sn;
    q[off + 1] = e * sn + o * cs;
    e = k[off]; o = k[off + 1];
    k[off]     = e * cs - o * sn;
    k[off + 1] = e * sn + o * cs;
}

// ---------------------------------------------------------------------------
// Causal flash attention, fp32. One query row per thread, BR=128 rows/block,
// BC=32 keys per smem tile. Scores kept in registers, smem read as float4
// broadcast so the loop stays FMA-pipe bound.
// ---------------------------------------------------------------------------
#define BR 128
#define BC 32

__global__ __launch_bounds__(128) void flash_kernel(
    const float* __restrict__ q, const float* __restrict__ k,
    const float* __restrict__ v, float* __restrict__ o)
{
    const int bh = blockIdx.y;
    const int b  = bh >> 4;
    const int h  = bh & 15;
    const int q0 = blockIdx.x * BR;
    const int row = threadIdx.x;
    const int qi  = q0 + row;

    __shared__ float Ks[BC][DK];
    __shared__ float Vs[BC][DK];

    // Load this thread's query row, prescaled by 1/sqrt(64)
    float qr[DK];
    {
        const float4* qb = (const float4*)(q + ((size_t)(b * SEQ + qi)) * D_MODEL + h * DK);
        #pragma unroll
        for (int d4 = 0; d4 < DK / 4; d4++) {
            float4 t = qb[d4];
            qr[4*d4+0] = t.x * 0.125f;
            qr[4*d4+1] = t.y * 0.125f;
            qr[4*d4+2] = t.z * 0.125f;
            qr[4*d4+3] = t.w * 0.125f;
        }
    }

    float oacc[DK];
    #pragma unroll
    for (int d = 0; d < DK; d++) oacc[d] = 0.f;
    float m = -1e30f, l = 0.f;

    const int kend = q0 + BR;   // causal: no key beyond last query row of block
    for (int k0 = 0; k0 < kend; k0 += BC) {
        __syncthreads();   // protect K/V tiles still being read
        for (int i = threadIdx.x; i < BC * DK / 4; i += 128) {
            int r  = i >> 4;       // 0..31
            int d4 = i & 15;       // 0..15
            size_t go = ((size_t)(b * SEQ + k0 + r)) * D_MODEL + h * DK + d4 * 4;
            ((float4*)&Ks[r][0])[d4] = *(const float4*)(k + go);
            ((float4*)&Vs[r][0])[d4] = *(const float4*)(v + go);
        }
        __syncthreads();

        float s[BC];
        float tmax = -1e30f;
        #pragma unroll
        for (int j = 0; j < BC; j++) {
            const float4* kj = (const float4*)&Ks[j][0];
            float s0 = 0.f, s1 = 0.f, s2 = 0.f, s3 = 0.f;
            #pragma unroll
            for (int d4 = 0; d4 < DK / 4; d4++) {
                float4 kv = kj[d4];
                s0 += qr[4*d4+0] * kv.x;
                s1 += qr[4*d4+1] * kv.y;
                s2 += qr[4*d4+2] * kv.z;
                s3 += qr[4*d4+3] * kv.w;
            }
            float sv = (s0 + s1) + (s2 + s3);
            if (k0 + j > qi) sv = -1e30f;   // causal mask on sequence index
            s[j] = sv;
            tmax = fmaxf(tmax, sv);
        }

        float mnew = fmaxf(m, tmax);
        float corr = __expf(m - mnew);
        l *= corr;
        #pragma unroll
        for (int d = 0; d < DK; d++) oacc[d] *= corr;

        #pragma unroll
        for (int j = 0; j < BC; j++) {
            float p = __expf(s[j] - mnew);
            l += p;
            const float4* vj = (const float4*)&Vs[j][0];
            #pragma unroll
            for (int d4 = 0; d4 < DK / 4; d4++) {
                float4 vv = vj[d4];
                oacc[4*d4+0] += p * vv.x;
                oacc[4*d4+1] += p * vv.y;
                oacc[4*d4+2] += p * vv.z;
                oacc[4*d4+3] += p * vv.w;
            }
        }
        m = mnew;
    }

    const float invl = 1.0f / l;
    float4* ob = (float4*)(o + ((size_t)(b * SEQ + qi)) * D_MODEL + h * DK);
    #pragma unroll
    for (int d4 = 0; d4 < DK / 4; d4++) {
        float4 t;
        t.x = oacc[4*d4+0] * invl;
        t.y = oacc[4*d4+1] * invl;
        t.z = oacc[4*d4+2] * invl;
        t.w = oacc[4*d4+3] * invl;
        ob[d4] = t;
    }
}

// ---------------------------------------------------------------------------
// Launch
// ---------------------------------------------------------------------------
extern "C" void kernel_launch(void* const* d_in, const int* in_sizes, int n_in,
                              void* d_out, int out_size)
{
    const float* x  = (const float*)d_in[0];
    const float* Wq = (const float*)d_in[1];
    const float* Wk = (const float*)d_in[2];
    const float* Wv = (const float*)d_in[3];
    const float* Wo = (const float*)d_in[4];
    const int*   tp = (const int*)d_in[5];
    float* out = (float*)d_out;

    float *qp, *kp, *vp, *op;
    cudaGetSymbolAddress((void**)&qp, g_q);
    cudaGetSymbolAddress((void**)&kp, g_k);
    cudaGetSymbolAddress((void**)&vp, g_v);
    cudaGetSymbolAddress((void**)&op, g_o);

    // 1) QKV projections (one launch, z selects weight/output)
    dim3 g1(D_MODEL / BN, M_TOT / BM, 3);
    sgemm_abT<<<g1, 256>>>(x, Wq, Wk, Wv, qp, kp, vp, M_TOT, D_MODEL, D_MODEL);

    // 2) RoPE on Q and K
    int npairs = BATCH * SEQ * NHEAD * (DK / 2);
    rope_kernel<<<(npairs + 255) / 256, 256>>>(qp, kp, tp);

    // 3) Causal flash attention -> O in [bs][h*64+d] layout
    flash_kernel<<<dim3(SEQ / BR, BATCH * NHEAD), 128>>>(qp, kp, vp, op);

    // 4) Output projection -> d_out
    dim3 g2(D_MODEL / BN, M_TOT / BM, 1);
    sgemm_abT<<<g2, 256>>>(op, Wo, Wo, Wo, out, out, out, M_TOT, D_MODEL, D_MODEL);
}